// round 16
// baseline (speedup 1.0000x reference)
#include <cuda_runtime.h>

// Graph_Learn: S[n,i,j] = exp(relu(sum_f |xm[n,i,f]-xm[n,j,f]|*a[f])) / colsum_i
// N=8, T=8 (slice t=4), V=512, F=64. Output (8,512,512) fp32.
// R16: monolithic barrier-free structure (R2) at 512 threads / 16 warps.
// Block = (n, 32 j-columns); full i-sweep; colsum + normalize in-block.
// xj in registers, a[] in smem (uniform LDS), scalar FADD+FFMA|abs| loop.

#define NB   8
#define TB   8
#define VB   512
#define FB   64
#define JT   32      // j-columns per block
#define NTHR 512
#define IGR  16      // i-groups = warps

// smem (floats): xm[512*64] | ev[512*32] | ps[16*32] | sa[64]
#define SM_E      (VB * FB)
#define SM_PS     (SM_E + VB * JT)
#define SM_A      (SM_PS + IGR * JT)
#define SM_FLOATS (SM_A + FB)            // 49728 floats = 198912 B

__global__ __launch_bounds__(NTHR, 1)
void graph_learn_kernel(const float* __restrict__ x,
                        const float* __restrict__ a,
                        float* __restrict__ out) {
    extern __shared__ float sm[];
    float* xm = sm;            // [512][64]
    float* ev = sm + SM_E;     // [512][32]
    float* ps = sm + SM_PS;    // [16][32]
    float* sa = sm + SM_A;     // [64]

    const int n   = blockIdx.y;
    const int jc  = blockIdx.x;
    const int tid = threadIdx.x;
    const int jl  = tid & (JT - 1);   // lane = j within chunk
    const int ig  = tid >> 5;         // warp = i-group (0..15)

    // cooperative load of middle time slice xm[n] (128 KB), float4
    const float4* __restrict__ xn4 =
        (const float4*)(x + ((size_t)n * TB + TB / 2) * VB * FB);
    float4* xm4 = (float4*)xm;
    #pragma unroll
    for (int q = 0; q < VB * FB / 4 / NTHR; q++)
        xm4[q * NTHR + tid] = xn4[q * NTHR + tid];
    if (tid < FB / 4) ((float4*)sa)[tid] = ((const float4*)a)[tid];
    __syncthreads();

    // per-thread j-row into registers (64 floats)
    const int j = jc * JT + jl;
    float xj[FB];
    {
        const float4* jr = (const float4*)(xm + j * FB);
        #pragma unroll
        for (int k = 0; k < FB / 4; k++) {
            float4 v = jr[k];
            xj[4*k+0] = v.x; xj[4*k+1] = v.y;
            xj[4*k+2] = v.z; xj[4*k+3] = v.w;
        }
    }

    const float4* sa4 = (const float4*)sa;
    float csum = 0.f;

    // mainloop: 16 outer iters x 2 i-rows, 8 scalar accumulators.
    // Per k-iter: 3 uniform LDS.128 (r0,r1,av) + 16 fma-family ops.
    #pragma unroll 1
    for (int m = 0; m < 16; m++) {
        const int i0 = m * 32 + ig;          // warp-uniform
        const int i1 = i0 + 16;
        const float4* r0 = (const float4*)(xm + i0 * FB);
        const float4* r1 = (const float4*)(xm + i1 * FB);
        float a00 = 0.f, a01 = 0.f, a02 = 0.f, a03 = 0.f;
        float a10 = 0.f, a11 = 0.f, a12 = 0.f, a13 = 0.f;
        #pragma unroll
        for (int k = 0; k < FB / 4; k++) {
            float4 av = sa4[k];
            float4 v0 = r0[k];
            float4 v1 = r1[k];
            a00 = fmaf(fabsf(v0.x - xj[4*k+0]), av.x, a00);
            a01 = fmaf(fabsf(v0.y - xj[4*k+1]), av.y, a01);
            a02 = fmaf(fabsf(v0.z - xj[4*k+2]), av.z, a02);
            a03 = fmaf(fabsf(v0.w - xj[4*k+3]), av.w, a03);
            a10 = fmaf(fabsf(v1.x - xj[4*k+0]), av.x, a10);
            a11 = fmaf(fabsf(v1.y - xj[4*k+1]), av.y, a11);
            a12 = fmaf(fabsf(v1.z - xj[4*k+2]), av.z, a12);
            a13 = fmaf(fabsf(v1.w - xj[4*k+3]), av.w, a13);
        }
        float s0 = (a00 + a01) + (a02 + a03);
        float s1 = (a10 + a11) + (a12 + a13);
        float e0 = __expf(fmaxf(s0, 0.f));
        float e1 = __expf(fmaxf(s1, 0.f));
        ev[i0 * JT + jl] = e0;    // lanes 0..31 -> banks 0..31, conflict-free
        ev[i1 * JT + jl] = e1;
        csum += e0 + e1;
    }

    // column-sum reduction across the 16 i-groups
    ps[ig * JT + jl] = csum;
    __syncthreads();
    float tot = 0.f;
    #pragma unroll
    for (int g = 0; g < IGR; g++) tot += ps[g * JT + jl];
    const float inv = 1.0f / tot;

    // normalize + store (warp writes 32 consecutive j -> 128B coalesced)
    float* __restrict__ outn = out + (size_t)n * VB * VB + j;
    #pragma unroll 1
    for (int m = 0; m < VB / IGR; m++) {
        const int i = m * IGR + ig;
        outn[(size_t)i * VB] = ev[i * JT + jl] * inv;
    }
}

extern "C" void kernel_launch(void* const* d_in, const int* in_sizes, int n_in,
                              void* d_out, int out_size) {
    const float* x = (const float*)d_in[0];   // (8,8,512,64) fp32
    const float* a = (const float*)d_in[1];   // (64,1) fp32
    float* out = (float*)d_out;               // (8,512,512) fp32

    const int smem_bytes = SM_FLOATS * (int)sizeof(float);  // ~198.9 KB
    cudaFuncSetAttribute(graph_learn_kernel,
                         cudaFuncAttributeMaxDynamicSharedMemorySize, smem_bytes);

    dim3 grid(VB / JT, NB);   // (16, 8) = 128 blocks, 1 per SM
    graph_learn_kernel<<<grid, NTHR, smem_bytes>>>(x, a, out);
}